// round 4
// baseline (speedup 1.0000x reference)
#include <cuda_runtime.h>
#include <cstdint>

#define T_LEN 8192
#define NTHREADS 256

__device__ __forceinline__ uint32_t rotl32(uint32_t x, int r) {
    return (x << r) | (x >> (32 - r));
}

// Threefry-2x32, 20 rounds, key = (0, 42) == jax.random.key(42).
// Returns x0 ^ x1 — the fold used by JAX's partitionable random_bits for
// bit_width <= 32 (jax_threefry_partitionable=True, default in modern JAX):
// counter64 = element index i -> block counters (hi=0, lo=i), outputs XORed.
__device__ __forceinline__ uint32_t threefry_xor(uint32_t c0, uint32_t c1) {
    const uint32_t ks0 = 0u, ks1 = 42u;
    const uint32_t ks2 = ks0 ^ ks1 ^ 0x1BD11BDAu;
    uint32_t x0 = c0 + ks0, x1 = c1 + ks1;
#define TF_R4(a,b,c,d) \
    x0 += x1; x1 = rotl32(x1,a); x1 ^= x0; \
    x0 += x1; x1 = rotl32(x1,b); x1 ^= x0; \
    x0 += x1; x1 = rotl32(x1,c); x1 ^= x0; \
    x0 += x1; x1 = rotl32(x1,d); x1 ^= x0;
    TF_R4(13,15,26,6);   x0 += ks1; x1 += ks2 + 1u;   // i=0
    TF_R4(17,29,16,24);  x0 += ks2; x1 += ks0 + 2u;   // i=1
    TF_R4(13,15,26,6);   x0 += ks0; x1 += ks1 + 3u;   // i=2
    TF_R4(17,29,16,24);  x0 += ks1; x1 += ks2 + 4u;   // i=3
    TF_R4(13,15,26,6);   x0 += ks2; x1 += ks0 + 5u;   // i=4
#undef TF_R4
    return x0 ^ x1;
}

__global__ __launch_bounds__(NTHREADS)
void midi_stats_mlp_kernel(const int* __restrict__ tokens,
                           const float* __restrict__ W1,
                           const float* __restrict__ b1,
                           const float* __restrict__ W2,
                           const float* __restrict__ b2,
                           float* __restrict__ out) {
    __shared__ int hist[128];
    __shared__ unsigned s_sum, s_ssq;
    __shared__ float stats[152];   // 150 used
    __shared__ float h[256];

    const int b = blockIdx.x;
    const int tid = threadIdx.x;

    if (tid < 128) hist[tid] = 0;
    if (tid == 0) { s_sum = 0u; s_ssq = 0u; }
    __syncthreads();

    // ---- Pass 1: histogram + integer moments (exact) ----
    const int4* tp = reinterpret_cast<const int4*>(tokens + (size_t)b * T_LEN);
    unsigned lsum = 0, lssq = 0;
#pragma unroll 4
    for (int i = tid; i < T_LEN / 4; i += NTHREADS) {
        int4 v = tp[i];
        atomicAdd(&hist[v.x & 127], 1);
        atomicAdd(&hist[v.y & 127], 1);
        atomicAdd(&hist[v.z & 127], 1);
        atomicAdd(&hist[v.w & 127], 1);
        lsum += (unsigned)(v.x + v.y + v.z + v.w);
        lssq += (unsigned)(v.x * v.x) + (unsigned)(v.y * v.y)
              + (unsigned)(v.z * v.z) + (unsigned)(v.w * v.w);
    }
    lsum = __reduce_add_sync(0xffffffffu, lsum);
    lssq = __reduce_add_sync(0xffffffffu, lssq);
    if ((tid & 31) == 0) {
        atomicAdd(&s_sum, lsum);
        atomicAdd(&s_ssq, lssq);
    }
    __syncthreads();

    // ---- Stage 2: assemble 150-dim stats vector ----
    if (tid < 128) {
        stats[tid] = (float)hist[tid] * (1.0f / 8192.0f);  // f32(8192 + 1e-8) == 8192
    } else if (tid == 128) {
        stats[128] = (float)((double)s_sum / 8192.0);      // mean
    } else if (tid == 129) {
        double m   = (double)s_sum / 8192.0;
        double var = ((double)s_ssq - (double)s_sum * m) / 8191.0;  // unbiased
        stats[129] = (float)sqrt(var);
    } else if (tid < 138) {
        stats[tid] = 0.0f;                                 // rhythm padding
    } else if (tid < 150) {
        // harmony: jax.random.uniform(key(42), (1024, 12)) — partitionable path:
        // counter64 = flat index -> threefry2x32(key, (0, idx)), outputs XORed.
        uint32_t idx = (uint32_t)(b * 12 + (tid - 138));
        uint32_t bits = threefry_xor(0u, idx);
        stats[tid] = __uint_as_float((bits >> 9) | 0x3F800000u) - 1.0f;
    }
    __syncthreads();

    // ---- Layer 1: h = relu(stats @ W1 + b1), one output per thread ----
    float acc = b1[tid];
#pragma unroll 10
    for (int s = 0; s < 150; s++)
        acc = fmaf(stats[s], W1[s * 256 + tid], acc);
    h[tid] = fmaxf(acc, 0.0f);
    __syncthreads();

    // ---- Layer 2: out = h @ W2 + b2, first 128 threads ----
    if (tid < 128) {
        float o = b2[tid];
#pragma unroll 8
        for (int k = 0; k < 256; k++)
            o = fmaf(h[k], W2[k * 128 + tid], o);
        out[(size_t)b * 128 + tid] = o;
    }
}

extern "C" void kernel_launch(void* const* d_in, const int* in_sizes, int n_in,
                              void* d_out, int out_size) {
    const int*   tokens = (const int*)d_in[0];
    const float* W1     = (const float*)d_in[1];
    const float* b1     = (const float*)d_in[2];
    const float* W2     = (const float*)d_in[3];
    const float* b2     = (const float*)d_in[4];
    float* out = (float*)d_out;
    midi_stats_mlp_kernel<<<1024, NTHREADS>>>(tokens, W1, b1, W2, b2, out);
}